// round 10
// baseline (speedup 1.0000x reference)
#include <cuda_runtime.h>
#include <cuda_bf16.h>
#include <stdint.h>
#include <math.h>

#define BB 4
#define CC 64
#define HH 128
#define WW 128
#define OO 64
#define PIX 16384

// ---------------- device scratch ----------------
__device__ float g_offset[BB*18*PIX];
__device__ float g_mask[BB*9*PIX];
__device__ float g_xt[BB*PIX*CC];     // x NHWC
__device__ float g_gt[BB*PIX*CC];     // guide NHWC
// B weights prepacked in mma fragment order
__device__ uint4 g_oBh[4608];   // offmod: (chunk*8 + ks*2 + nhalf)*32 + lane
__device__ uint4 g_oBl[4608];
__device__ uint4 g_dBh[4608];   // deform: (kk*16 + ks*4 + nhalf*2 + p)*32 + lane
__device__ uint4 g_dBl[4608];

// ---------------- helpers ----------------
__device__ __forceinline__ uint32_t smem_u32(const void* p){
    uint32_t a;
    asm("{ .reg .u64 t; cvta.to.shared.u64 t, %1; cvt.u32.u64 %0, t; }" : "=r"(a) : "l"(p));
    return a;
}
__device__ __forceinline__ void ldsm4(uint32_t& r0, uint32_t& r1, uint32_t& r2, uint32_t& r3, uint32_t a){
    asm volatile("ldmatrix.sync.aligned.m8n8.x4.shared.b16 {%0,%1,%2,%3}, [%4];"
                 : "=r"(r0),"=r"(r1),"=r"(r2),"=r"(r3) : "r"(a));
}
__device__ __forceinline__ void mma16816(float* d, uint32_t a0, uint32_t a1, uint32_t a2, uint32_t a3,
                                         uint32_t b0, uint32_t b1){
    asm volatile("mma.sync.aligned.m16n8k16.row.col.f32.bf16.bf16.f32 "
                 "{%0,%1,%2,%3}, {%4,%5,%6,%7}, {%8,%9}, {%0,%1,%2,%3};"
                 : "+f"(d[0]),"+f"(d[1]),"+f"(d[2]),"+f"(d[3])
                 : "r"(a0),"r"(a1),"r"(a2),"r"(a3),"r"(b0),"r"(b1));
}
__device__ __forceinline__ void sts4(uint32_t a, uint32_t x, uint32_t y, uint32_t z, uint32_t w){
    asm volatile("st.shared.v4.u32 [%0], {%1,%2,%3,%4};" :: "r"(a),"r"(x),"r"(y),"r"(z),"r"(w) : "memory");
}
__device__ __forceinline__ void sts2(uint32_t a, uint32_t x, uint32_t y){
    asm volatile("st.shared.v2.u32 [%0], {%1,%2};" :: "r"(a),"r"(x),"r"(y) : "memory");
}
__device__ __forceinline__ uint32_t pk(float lo_e, float hi_e){
    uint32_t r;
    asm("cvt.rn.bf16x2.f32 %0, %1, %2;" : "=r"(r) : "f"(hi_e), "f"(lo_e));
    return r;
}
__device__ __forceinline__ float btrunc(float v){ return __bfloat162float(__float2bfloat16(v)); }

// ---------------------------------------------------------------------------
// Kernel 0: NCHW -> NHWC transpose (x and guide), vectorized both directions
// ---------------------------------------------------------------------------
__global__ void k_transpose(const float* __restrict__ x, const float* __restrict__ g){
    __shared__ float s[64*129];
    int h = blockIdx.x, b = blockIdx.y;
    const float* src = blockIdx.z ? g : x;
    float* dst       = blockIdx.z ? g_gt : g_xt;
    const float* xp = src + ((size_t)b*CC)*PIX + (size_t)h*WW;
    for (int i = threadIdx.x; i < 2048; i += 256) {
        int c = i >> 5, x4 = (i & 31) * 4;
        float4 v = *(const float4*)(xp + (size_t)c*PIX + x4);
        s[c*129 + x4+0]=v.x; s[c*129 + x4+1]=v.y; s[c*129 + x4+2]=v.z; s[c*129 + x4+3]=v.w;
    }
    __syncthreads();
    float* op = dst + ((size_t)(b*HH + h)*WW)*CC;
    for (int i = threadIdx.x; i < 2048; i += 256) {
        int xx = i >> 4, c4 = (i & 15) * 4;
        float4 v;
        v.x = s[(c4+0)*129 + xx];
        v.y = s[(c4+1)*129 + xx];
        v.z = s[(c4+2)*129 + xx];
        v.w = s[(c4+3)*129 + xx];
        *(float4*)(op + (size_t)xx*CC + c4) = v;
    }
}

// ---------------------------------------------------------------------------
// Kernel 1: weight prep — fp32 -> bf16 hi/lo, packed in mma fragment order.
// ---------------------------------------------------------------------------
__global__ void k_prepw(const float* __restrict__ w_off, const float* __restrict__ w_mod,
                        const float* __restrict__ w_reg){
    int i = blockIdx.x*256 + threadIdx.x;
    if (i >= 18432) return;
    int q = i & 3, L = (i >> 2) & 31;
    { // offmod: i = ((chunk*8 + ks*2 + nhalf)*32 + L)*4 + q
        int nhalf = (i >> 7) & 1, ks = (i >> 8) & 3, chunk = i >> 10;
        int kk = chunk >> 1, half = chunk & 1;
        int oc = nhalf*16 + ((q >> 1) & 1)*8 + (L >> 2);
        int ch = ks*16 + (q & 1)*8 + (L & 3)*2;
        int c0 = half*64 + ch;
        float w0 = 0.f, w1 = 0.f;
        if (oc < 18)      { w0 = w_off[(oc*128 + c0)*9 + kk];       w1 = w_off[(oc*128 + c0 + 1)*9 + kk]; }
        else if (oc < 27) { w0 = w_mod[((oc-18)*128 + c0)*9 + kk];  w1 = w_mod[((oc-18)*128 + c0 + 1)*9 + kk]; }
        float h0 = btrunc(w0), h1 = btrunc(w1);
        ((uint32_t*)g_oBh)[i] = pk(h0, h1);
        ((uint32_t*)g_oBl)[i] = pk(w0 - h0, w1 - h1);
    }
    { // deform: i = ((kk*16 + ks*4 + nhalf*2 + p)*32 + L)*4 + q
        int p = (i >> 7) & 1, nhalf = (i >> 8) & 1, ks = (i >> 9) & 3, kk = i >> 11;
        int oc = nhalf*32 + p*16 + ((q >> 1) & 1)*8 + (L >> 2);
        int ch = ks*16 + (q & 1)*8 + (L & 3)*2;
        float w0 = w_reg[(oc*64 + ch)*9 + kk], w1 = w_reg[(oc*64 + ch + 1)*9 + kk];
        float h0 = btrunc(w0), h1 = btrunc(w1);
        ((uint32_t*)g_dBh)[i] = pk(h0, h1);
        ((uint32_t*)g_dBl)[i] = pk(w0 - h0, w1 - h1);
    }
}

// ---------------------------------------------------------------------------
// Kernel 2: offset+modulator conv (M=128, N=32(27), K=1152).
// Single-buffered A (32KB) + direct-LDG fragment B -> 4 CTAs/SM. (R8, proven)
// ---------------------------------------------------------------------------
#define OM_AH 0
#define OM_AL 16384
#define OM_SMEM (32768 + 128)

__global__ __launch_bounds__(256,4) void k_offmod(const float* __restrict__ b_off,
                                                  const float* __restrict__ b_mod)
{
    extern __shared__ char smem_raw[];
    uint32_t sbr = smem_u32(smem_raw);
    uint32_t sb  = (sbr + 127) & ~127u;

    int t = threadIdx.x, wid = t >> 5, lid = t & 31;
    int mwid = wid & 3, nhalf = wid >> 2;
    int h = blockIdx.x, b = blockIdx.y;

    uint32_t aRowSel = (lid & 7) + ((lid >> 3) & 1) * 8;
    uint32_t aColSel = ((lid >> 4) & 1) * 16;
    uint32_t swz = (lid & 7) * 16;

    float acc[16];
#pragma unroll
    for (int i = 0; i < 16; i++) acc[i] = 0.f;

    for (int chunk = 0; chunk < 18; chunk++) {
        int kk = chunk >> 1, half = chunk & 1;
        int dy = kk/3 - 1, dx = kk%3 - 1;
        if (chunk) __syncthreads();
        { // stage A: [128 px][64 ch] of x/guide (NHWC) at (h+dy, px+dx)
            int hy = h + dy;
            bool rowok = (hy >= 0) && (hy < HH);
            const float* rowp = (half ? g_gt : g_xt) + (((size_t)b*HH + (rowok?hy:0))*WW)*CC;
#pragma unroll
            for (int jj = 0; jj < 4; jj++) {
                int i = jj*256 + t;
                int px = i >> 3, c8 = i & 7;
                int gx = px + dx;
                float v0=0,v1=0,v2=0,v3=0,v4=0,v5=0,v6=0,v7=0;
                if (rowok && gx >= 0 && gx < WW) {
                    const float4* p = (const float4*)(rowp + (size_t)gx*CC + c8*8);
                    float4 a = p[0], c = p[1];
                    v0=a.x; v1=a.y; v2=a.z; v3=a.w; v4=c.x; v5=c.y; v6=c.z; v7=c.w;
                }
                float w0=btrunc(v0),w1=btrunc(v1),w2=btrunc(v2),w3=btrunc(v3);
                float w4=btrunc(v4),w5=btrunc(v5),w6=btrunc(v6),w7=btrunc(v7);
                uint32_t off = px*128 + ((c8 ^ (px & 7)) * 16);
                sts4(sb + OM_AH + off, pk(v0,v1), pk(v2,v3), pk(v4,v5), pk(v6,v7));
                sts4(sb + OM_AL + off, pk(v0-w0,v1-w1), pk(v2-w2,v3-w3),
                                       pk(v4-w4,v5-w5), pk(v6-w6,v7-w7));
            }
        }
        __syncthreads();

#pragma unroll
        for (int ks = 0; ks < 4; ks++) {
            uint4 BH = g_oBh[(chunk*8 + ks*2 + nhalf)*32 + lid];
            uint4 BL = g_oBl[(chunk*8 + ks*2 + nhalf)*32 + lid];
            uint32_t ah[8], al[8];
#pragma unroll
            for (int m = 0; m < 2; m++) {
                uint32_t R = mwid*32 + m*16 + aRowSel;
                uint32_t aa = sb + OM_AH + R*128 + ((ks*32 + aColSel) ^ swz);
                ldsm4(ah[m*4+0], ah[m*4+1], ah[m*4+2], ah[m*4+3], aa);
                ldsm4(al[m*4+0], al[m*4+1], al[m*4+2], al[m*4+3], aa + 16384);
            }
#pragma unroll
            for (int m = 0; m < 2; m++) {
                float* d0 = acc + (m*2+0)*4;
                float* d1 = acc + (m*2+1)*4;
                mma16816(d0, ah[m*4+0],ah[m*4+1],ah[m*4+2],ah[m*4+3], BH.x, BH.y);
                mma16816(d0, al[m*4+0],al[m*4+1],al[m*4+2],al[m*4+3], BH.x, BH.y);
                mma16816(d0, ah[m*4+0],ah[m*4+1],ah[m*4+2],ah[m*4+3], BL.x, BL.y);
                mma16816(d1, ah[m*4+0],ah[m*4+1],ah[m*4+2],ah[m*4+3], BH.z, BH.w);
                mma16816(d1, al[m*4+0],al[m*4+1],al[m*4+2],al[m*4+3], BH.z, BH.w);
                mma16816(d1, ah[m*4+0],ah[m*4+1],ah[m*4+2],ah[m*4+3], BL.z, BL.w);
            }
        }
    }

    // epilogue
    int g = lid >> 2, tig = lid & 3;
    int pixbase = h*WW;
#pragma unroll
    for (int m = 0; m < 2; m++)
#pragma unroll
    for (int n = 0; n < 2; n++)
#pragma unroll
    for (int r = 0; r < 4; r++) {
        int px = mwid*32 + m*16 + g + (r>>1)*8;
        int oc = nhalf*16 + n*8 + 2*tig + (r&1);
        float v = acc[(m*2+n)*4 + r];
        int pix = pixbase + px;
        if (oc < 18) {
            g_offset[(size_t)(b*18 + oc)*PIX + pix] = v + b_off[oc];
        } else if (oc < 27) {
            float z = v + b_mod[oc-18];
            g_mask[(size_t)(b*9 + oc-18)*PIX + pix] = 2.f / (1.f + expf(-z));
        }
    }
}

// ---------------------------------------------------------------------------
// Kernel 3: deformable conv (M=128, N=64, K=576).
// Single-buffered A (32KB) + params (4KB) -> 37KB smem; forced 64 regs -> 4 CTAs.
// Warp-local params (lanes<16, __syncwarp). B fragments loaded in 2 halves.
// ---------------------------------------------------------------------------
#define DF_AH 0
#define DF_AL 16384
#define DF_PR 32768
#define DF_SMEM (36864 + 128)

__global__ __launch_bounds__(256,4) void k_deform(float* __restrict__ out)
{
    extern __shared__ char smem_raw[];
    uint32_t sbr = smem_u32(smem_raw);
    uint32_t sb  = (sbr + 127) & ~127u;
    char* sm0 = smem_raw + (sb - sbr);
    int*   spi = (int*)(sm0 + DF_PR);
    float* spf = (float*)(sm0 + DF_PR);

    int t = threadIdx.x, wid = t >> 5, lid = t & 31;
    int mwid = wid & 3, nhalf = wid >> 2;
    int h = blockIdx.x, b = blockIdx.y;

    uint32_t aRowSel = (lid & 7) + ((lid >> 3) & 1) * 8;
    uint32_t aColSel = ((lid >> 4) & 1) * 16;
    uint32_t swz = (lid & 7) * 16;

    const float4* xb4 = (const float4*)(g_xt + (size_t)b*PIX*CC);

    float acc[32];
#pragma unroll
    for (int i = 0; i < 32; i++) acc[i] = 0.f;

    for (int kk = 0; kk < 9; kk++) {
        if (kk) __syncthreads();   // A buffer free after previous MMA
        // warp-local params: lanes<16 compute the 16 px this warp gathers
        if (lid < 16) {
            int px = (wid << 1) + (lid & 1) + ((lid >> 1) << 4);
            int pix = h*WW + px;
            float oy = g_offset[((size_t)(b*18 + 2*kk  ))*PIX + pix];
            float ox = g_offset[((size_t)(b*18 + 2*kk+1))*PIX + pix];
            float m  = g_mask  [((size_t)(b*9  + kk    ))*PIX + pix];
            int ky = kk/3, kx = kk - ky*3;
            float py  = oy + (float)(ky + h - 1);
            float pxf = ox + (float)(kx + px - 1);
            float y0f = floorf(py), x0f = floorf(pxf);
            int y0 = (int)y0f, x0 = (int)x0f;
            int y1 = y0 + 1,   x1 = x0 + 1;
            float wy1 = py - y0f,  wx1 = pxf - x0f;
            float wy0 = 1.f - wy1, wx0 = 1.f - wx1;
            bool vy0 = (y0>=0 && y0<HH), vy1 = (y1>=0 && y1<HH);
            bool vx0 = (x0>=0 && x0<WW), vx1 = (x1>=0 && x1<WW);
            int y0c = min(max(y0,0),HH-1), y1c = min(max(y1,0),HH-1);
            int x0c = min(max(x0,0),WW-1), x1c = min(max(x1,0),WW-1);
            int base = px*8;
            spi[base+0] = (y0c*WW + x0c)*16;
            spi[base+1] = (y0c*WW + x1c)*16;
            spi[base+2] = (y1c*WW + x0c)*16;
            spi[base+3] = (y1c*WW + x1c)*16;
            spf[base+4] = (vy0&&vx0) ? wy0*wx0*m : 0.f;
            spf[base+5] = (vy0&&vx1) ? wy0*wx1*m : 0.f;
            spf[base+6] = (vy1&&vx0) ? wy1*wx0*m : 0.f;
            spf[base+7] = (vy1&&vx1) ? wy1*wx1*m : 0.f;
        }
        __syncwarp();
        // gather: 8 iters, warp w covers px = it*16 + w*2 + {0,1}
#pragma unroll
        for (int it = 0; it < 8; it++) {
            int j = it*256 + t;
            int px = j >> 4, l16 = j & 15;
            int base = px*8;
            int i00 = spi[base+0], i01 = spi[base+1], i10 = spi[base+2], i11 = spi[base+3];
            float g00 = spf[base+4], g01 = spf[base+5], g10 = spf[base+6], g11 = spf[base+7];
            float4 a = xb4[i00 + l16];
            float4 c = xb4[i01 + l16];
            float4 d = xb4[i10 + l16];
            float4 e = xb4[i11 + l16];
            float v0 = g00*a.x + g01*c.x + g10*d.x + g11*e.x;
            float v1 = g00*a.y + g01*c.y + g10*d.y + g11*e.y;
            float v2 = g00*a.z + g01*c.z + g10*d.z + g11*e.z;
            float v3 = g00*a.w + g01*c.w + g10*d.w + g11*e.w;
            float w0=btrunc(v0), w1=btrunc(v1), w2=btrunc(v2), w3=btrunc(v3);
            uint32_t off = px*128 + ((l16*8) ^ ((px & 7)*16));
            sts2(sb + DF_AH + off, pk(v0,v1), pk(v2,v3));
            sts2(sb + DF_AL + off, pk(v0-w0,v1-w1), pk(v2-w2,v3-w3));
        }
        __syncthreads();

#pragma unroll
        for (int ks = 0; ks < 4; ks++) {
            int bi = (kk*16 + ks*4 + nhalf*2)*32 + lid;
            uint32_t ah[8], al[8];
#pragma unroll
            for (int m = 0; m < 2; m++) {
                uint32_t R = mwid*32 + m*16 + aRowSel;
                uint32_t aa = sb + DF_AH + R*128 + ((ks*32 + aColSel) ^ swz);
                ldsm4(ah[m*4+0], ah[m*4+1], ah[m*4+2], ah[m*4+3], aa);
                ldsm4(al[m*4+0], al[m*4+1], al[m*4+2], al[m*4+3], aa + 16384);
            }
            { // first N-16 half
                uint4 BH = g_dBh[bi], BL = g_dBl[bi];
#pragma unroll
                for (int m = 0; m < 2; m++) {
                    float* d0 = acc + (m*4+0)*4;
                    float* d1 = acc + (m*4+1)*4;
                    mma16816(d0, ah[m*4+0],ah[m*4+1],ah[m*4+2],ah[m*4+3], BH.x, BH.y);
                    mma16816(d0, al[m*4+0],al[m*4+1],al[m*4+2],al[m*4+3], BH.x, BH.y);
                    mma16816(d0, ah[m*4+0],ah[m*4+1],ah[m*4+2],ah[m*4+3], BL.x, BL.y);
                    mma16816(d1, ah[m*4+0],ah[m*4+1],ah[m*4+2],ah[m*4+3], BH.z, BH.w);
                    mma16816(d1, al[m*4+0],al[m*4+1],al[m*4+2],al[m*4+3], BH.z, BH.w);
                    mma16816(d1, ah[m*4+0],ah[m*4+1],ah[m*4+2],ah[m*4+3], BL.z, BL.w);
                }
            }
            { // second N-16 half
                uint4 BH = g_dBh[bi + 32], BL = g_dBl[bi + 32];
#pragma unroll
                for (int m = 0; m < 2; m++) {
                    float* d2 = acc + (m*4+2)*4;
                    float* d3 = acc + (m*4+3)*4;
                    mma16816(d2, ah[m*4+0],ah[m*4+1],ah[m*4+2],ah[m*4+3], BH.x, BH.y);
                    mma16816(d2, al[m*4+0],al[m*4+1],al[m*4+2],al[m*4+3], BH.x, BH.y);
                    mma16816(d2, ah[m*4+0],ah[m*4+1],ah[m*4+2],ah[m*4+3], BL.x, BL.y);
                    mma16816(d3, ah[m*4+0],ah[m*4+1],ah[m*4+2],ah[m*4+3], BH.z, BH.w);
                    mma16816(d3, al[m*4+0],al[m*4+1],al[m*4+2],al[m*4+3], BH.z, BH.w);
                    mma16816(d3, ah[m*4+0],ah[m*4+1],ah[m*4+2],ah[m*4+3], BL.z, BL.w);
                }
            }
        }
    }

    // epilogue
    int g = lid >> 2, tig = lid & 3;
    size_t ob = (size_t)b*64*PIX + (size_t)h*WW;
#pragma unroll
    for (int n = 0; n < 4; n++)
#pragma unroll
    for (int m = 0; m < 2; m++)
#pragma unroll
    for (int r = 0; r < 4; r++) {
        int px = mwid*32 + m*16 + g + (r>>1)*8;
        int oc = nhalf*32 + n*8 + 2*tig + (r&1);
        out[ob + (size_t)oc*PIX + px] = acc[(m*4+n)*4 + r];
    }
}

// ---------------------------------------------------------------------------
extern "C" void kernel_launch(void* const* d_in, const int* in_sizes, int n_in,
                              void* d_out, int out_size)
{
    const float* x     = (const float*)d_in[0];
    const float* guide = (const float*)d_in[1];
    const float* w_off = (const float*)d_in[2];
    const float* b_off = (const float*)d_in[3];
    const float* w_mod = (const float*)d_in[4];
    const float* b_mod = (const float*)d_in[5];
    const float* w_reg = (const float*)d_in[6];
    float* out = (float*)d_out;

    cudaFuncSetAttribute(k_offmod, cudaFuncAttributeMaxDynamicSharedMemorySize, OM_SMEM);
    cudaFuncSetAttribute(k_deform, cudaFuncAttributeMaxDynamicSharedMemorySize, DF_SMEM);

    k_transpose<<<dim3(HH, BB, 2), 256>>>(x, guide);
    k_prepw    <<<72, 256>>>(w_off, w_mod, w_reg);
    k_offmod   <<<dim3(HH, BB), 256, OM_SMEM>>>(b_off, b_mod);
    k_deform   <<<dim3(HH, BB), 256, DF_SMEM>>>(out);
}

// round 11
// speedup vs baseline: 1.1185x; 1.1185x over previous
#include <cuda_runtime.h>
#include <cuda_bf16.h>
#include <stdint.h>
#include <math.h>

#define BB 4
#define CC 64
#define HH 128
#define WW 128
#define OO 64
#define PIX 16384

// ---------------- device scratch ----------------
__device__ float g_offset[BB*18*PIX];
__device__ float g_mask[BB*9*PIX];
__device__ float g_xt[BB*PIX*CC];     // x NHWC
__device__ float g_gt[BB*PIX*CC];     // guide NHWC
// B weights prepacked in mma fragment order
__device__ uint4 g_oBh[4608];   // offmod: (chunk*8 + ks*2 + nhalf)*32 + lane
__device__ uint4 g_oBl[4608];
__device__ uint4 g_dBh[4608];   // deform: (kk*16 + ks*4 + nhalf*2 + p)*32 + lane
__device__ uint4 g_dBl[4608];

// ---------------- helpers ----------------
__device__ __forceinline__ uint32_t smem_u32(const void* p){
    uint32_t a;
    asm("{ .reg .u64 t; cvta.to.shared.u64 t, %1; cvt.u32.u64 %0, t; }" : "=r"(a) : "l"(p));
    return a;
}
__device__ __forceinline__ void ldsm4(uint32_t& r0, uint32_t& r1, uint32_t& r2, uint32_t& r3, uint32_t a){
    asm volatile("ldmatrix.sync.aligned.m8n8.x4.shared.b16 {%0,%1,%2,%3}, [%4];"
                 : "=r"(r0),"=r"(r1),"=r"(r2),"=r"(r3) : "r"(a));
}
__device__ __forceinline__ void mma16816(float* d, uint32_t a0, uint32_t a1, uint32_t a2, uint32_t a3,
                                         uint32_t b0, uint32_t b1){
    asm volatile("mma.sync.aligned.m16n8k16.row.col.f32.bf16.bf16.f32 "
                 "{%0,%1,%2,%3}, {%4,%5,%6,%7}, {%8,%9}, {%0,%1,%2,%3};"
                 : "+f"(d[0]),"+f"(d[1]),"+f"(d[2]),"+f"(d[3])
                 : "r"(a0),"r"(a1),"r"(a2),"r"(a3),"r"(b0),"r"(b1));
}
__device__ __forceinline__ void sts4(uint32_t a, uint32_t x, uint32_t y, uint32_t z, uint32_t w){
    asm volatile("st.shared.v4.u32 [%0], {%1,%2,%3,%4};" :: "r"(a),"r"(x),"r"(y),"r"(z),"r"(w) : "memory");
}
__device__ __forceinline__ void sts2(uint32_t a, uint32_t x, uint32_t y){
    asm volatile("st.shared.v2.u32 [%0], {%1,%2};" :: "r"(a),"r"(x),"r"(y) : "memory");
}
__device__ __forceinline__ uint32_t pk(float lo_e, float hi_e){
    uint32_t r;
    asm("cvt.rn.bf16x2.f32 %0, %1, %2;" : "=r"(r) : "f"(hi_e), "f"(lo_e));
    return r;
}
__device__ __forceinline__ float btrunc(float v){ return __bfloat162float(__float2bfloat16(v)); }

// ---------------------------------------------------------------------------
// Kernel 0: NCHW -> NHWC transpose (x and guide), vectorized both directions
// ---------------------------------------------------------------------------
__global__ void k_transpose(const float* __restrict__ x, const float* __restrict__ g){
    __shared__ float s[64*129];
    int h = blockIdx.x, b = blockIdx.y;
    const float* src = blockIdx.z ? g : x;
    float* dst       = blockIdx.z ? g_gt : g_xt;
    const float* xp = src + ((size_t)b*CC)*PIX + (size_t)h*WW;
    for (int i = threadIdx.x; i < 2048; i += 256) {
        int c = i >> 5, x4 = (i & 31) * 4;
        float4 v = *(const float4*)(xp + (size_t)c*PIX + x4);
        s[c*129 + x4+0]=v.x; s[c*129 + x4+1]=v.y; s[c*129 + x4+2]=v.z; s[c*129 + x4+3]=v.w;
    }
    __syncthreads();
    float* op = dst + ((size_t)(b*HH + h)*WW)*CC;
    for (int i = threadIdx.x; i < 2048; i += 256) {
        int xx = i >> 4, c4 = (i & 15) * 4;
        float4 v;
        v.x = s[(c4+0)*129 + xx];
        v.y = s[(c4+1)*129 + xx];
        v.z = s[(c4+2)*129 + xx];
        v.w = s[(c4+3)*129 + xx];
        *(float4*)(op + (size_t)xx*CC + c4) = v;
    }
}

// ---------------------------------------------------------------------------
// Kernel 1: weight prep — fp32 -> bf16 hi/lo, packed in mma fragment order.
// ---------------------------------------------------------------------------
__global__ void k_prepw(const float* __restrict__ w_off, const float* __restrict__ w_mod,
                        const float* __restrict__ w_reg){
    int i = blockIdx.x*256 + threadIdx.x;
    if (i >= 18432) return;
    int q = i & 3, L = (i >> 2) & 31;
    { // offmod: i = ((chunk*8 + ks*2 + nhalf)*32 + L)*4 + q
        int nhalf = (i >> 7) & 1, ks = (i >> 8) & 3, chunk = i >> 10;
        int kk = chunk >> 1, half = chunk & 1;
        int oc = nhalf*16 + ((q >> 1) & 1)*8 + (L >> 2);
        int ch = ks*16 + (q & 1)*8 + (L & 3)*2;
        int c0 = half*64 + ch;
        float w0 = 0.f, w1 = 0.f;
        if (oc < 18)      { w0 = w_off[(oc*128 + c0)*9 + kk];       w1 = w_off[(oc*128 + c0 + 1)*9 + kk]; }
        else if (oc < 27) { w0 = w_mod[((oc-18)*128 + c0)*9 + kk];  w1 = w_mod[((oc-18)*128 + c0 + 1)*9 + kk]; }
        float h0 = btrunc(w0), h1 = btrunc(w1);
        ((uint32_t*)g_oBh)[i] = pk(h0, h1);
        ((uint32_t*)g_oBl)[i] = pk(w0 - h0, w1 - h1);
    }
    { // deform: i = ((kk*16 + ks*4 + nhalf*2 + p)*32 + L)*4 + q
        int p = (i >> 7) & 1, nhalf = (i >> 8) & 1, ks = (i >> 9) & 3, kk = i >> 11;
        int oc = nhalf*32 + p*16 + ((q >> 1) & 1)*8 + (L >> 2);
        int ch = ks*16 + (q & 1)*8 + (L & 3)*2;
        float w0 = w_reg[(oc*64 + ch)*9 + kk], w1 = w_reg[(oc*64 + ch + 1)*9 + kk];
        float h0 = btrunc(w0), h1 = btrunc(w1);
        ((uint32_t*)g_dBh)[i] = pk(h0, h1);
        ((uint32_t*)g_dBl)[i] = pk(w0 - h0, w1 - h1);
    }
}

// ---------------------------------------------------------------------------
// Kernel 2: offset+modulator conv (M=128, N=32(27), K=1152).
// Single-buffered A (32KB) + direct-LDG fragment B -> 4 CTAs/SM. (R8, proven)
// ---------------------------------------------------------------------------
#define OM_AH 0
#define OM_AL 16384
#define OM_SMEM (32768 + 128)

__global__ __launch_bounds__(256,4) void k_offmod(const float* __restrict__ b_off,
                                                  const float* __restrict__ b_mod)
{
    extern __shared__ char smem_raw[];
    uint32_t sbr = smem_u32(smem_raw);
    uint32_t sb  = (sbr + 127) & ~127u;

    int t = threadIdx.x, wid = t >> 5, lid = t & 31;
    int mwid = wid & 3, nhalf = wid >> 2;
    int h = blockIdx.x, b = blockIdx.y;

    uint32_t aRowSel = (lid & 7) + ((lid >> 3) & 1) * 8;
    uint32_t aColSel = ((lid >> 4) & 1) * 16;
    uint32_t swz = (lid & 7) * 16;

    float acc[16];
#pragma unroll
    for (int i = 0; i < 16; i++) acc[i] = 0.f;

    for (int chunk = 0; chunk < 18; chunk++) {
        int kk = chunk >> 1, half = chunk & 1;
        int dy = kk/3 - 1, dx = kk%3 - 1;
        if (chunk) __syncthreads();
        { // stage A: [128 px][64 ch] of x/guide (NHWC) at (h+dy, px+dx)
            int hy = h + dy;
            bool rowok = (hy >= 0) && (hy < HH);
            const float* rowp = (half ? g_gt : g_xt) + (((size_t)b*HH + (rowok?hy:0))*WW)*CC;
#pragma unroll
            for (int jj = 0; jj < 4; jj++) {
                int i = jj*256 + t;
                int px = i >> 3, c8 = i & 7;
                int gx = px + dx;
                float v0=0,v1=0,v2=0,v3=0,v4=0,v5=0,v6=0,v7=0;
                if (rowok && gx >= 0 && gx < WW) {
                    const float4* p = (const float4*)(rowp + (size_t)gx*CC + c8*8);
                    float4 a = p[0], c = p[1];
                    v0=a.x; v1=a.y; v2=a.z; v3=a.w; v4=c.x; v5=c.y; v6=c.z; v7=c.w;
                }
                float w0=btrunc(v0),w1=btrunc(v1),w2=btrunc(v2),w3=btrunc(v3);
                float w4=btrunc(v4),w5=btrunc(v5),w6=btrunc(v6),w7=btrunc(v7);
                uint32_t off = px*128 + ((c8 ^ (px & 7)) * 16);
                sts4(sb + OM_AH + off, pk(v0,v1), pk(v2,v3), pk(v4,v5), pk(v6,v7));
                sts4(sb + OM_AL + off, pk(v0-w0,v1-w1), pk(v2-w2,v3-w3),
                                       pk(v4-w4,v5-w5), pk(v6-w6,v7-w7));
            }
        }
        __syncthreads();

#pragma unroll
        for (int ks = 0; ks < 4; ks++) {
            uint4 BH = g_oBh[(chunk*8 + ks*2 + nhalf)*32 + lid];
            uint4 BL = g_oBl[(chunk*8 + ks*2 + nhalf)*32 + lid];
            uint32_t ah[8], al[8];
#pragma unroll
            for (int m = 0; m < 2; m++) {
                uint32_t R = mwid*32 + m*16 + aRowSel;
                uint32_t aa = sb + OM_AH + R*128 + ((ks*32 + aColSel) ^ swz);
                ldsm4(ah[m*4+0], ah[m*4+1], ah[m*4+2], ah[m*4+3], aa);
                ldsm4(al[m*4+0], al[m*4+1], al[m*4+2], al[m*4+3], aa + 16384);
            }
#pragma unroll
            for (int m = 0; m < 2; m++) {
                float* d0 = acc + (m*2+0)*4;
                float* d1 = acc + (m*2+1)*4;
                mma16816(d0, ah[m*4+0],ah[m*4+1],ah[m*4+2],ah[m*4+3], BH.x, BH.y);
                mma16816(d0, al[m*4+0],al[m*4+1],al[m*4+2],al[m*4+3], BH.x, BH.y);
                mma16816(d0, ah[m*4+0],ah[m*4+1],ah[m*4+2],ah[m*4+3], BL.x, BL.y);
                mma16816(d1, ah[m*4+0],ah[m*4+1],ah[m*4+2],ah[m*4+3], BH.z, BH.w);
                mma16816(d1, al[m*4+0],al[m*4+1],al[m*4+2],al[m*4+3], BH.z, BH.w);
                mma16816(d1, ah[m*4+0],ah[m*4+1],ah[m*4+2],ah[m*4+3], BL.z, BL.w);
            }
        }
    }

    // epilogue
    int g = lid >> 2, tig = lid & 3;
    int pixbase = h*WW;
#pragma unroll
    for (int m = 0; m < 2; m++)
#pragma unroll
    for (int n = 0; n < 2; n++)
#pragma unroll
    for (int r = 0; r < 4; r++) {
        int px = mwid*32 + m*16 + g + (r>>1)*8;
        int oc = nhalf*16 + n*8 + 2*tig + (r&1);
        float v = acc[(m*2+n)*4 + r];
        int pix = pixbase + px;
        if (oc < 18) {
            g_offset[(size_t)(b*18 + oc)*PIX + pix] = v + b_off[oc];
        } else if (oc < 27) {
            float z = v + b_mod[oc-18];
            g_mask[(size_t)(b*9 + oc-18)*PIX + pix] = 2.f / (1.f + expf(-z));
        }
    }
}

// ---------------------------------------------------------------------------
// Kernel 3: deformable conv (M=128, N=64, K=576), pipelined. (R7/R8, proven)
// A double-buffered (swizzled), params double-buffered (2-ahead), B direct-LDG.
// ---------------------------------------------------------------------------
#define DF_PB  0
#define DF_A0H 8192
#define DF_A0L 24576
#define DF_A1H 40960
#define DF_A1L 57344
#define DF_SMEM (73728 + 128)

__global__ __launch_bounds__(256,3) void k_deform(float* __restrict__ out)
{
    extern __shared__ char smem_raw[];
    uint32_t sbr = smem_u32(smem_raw);
    uint32_t sb  = (sbr + 127) & ~127u;
    char* sm0 = smem_raw + (sb - sbr);
    int*   spi = (int*)(sm0 + DF_PB);
    float* spf = (float*)(sm0 + DF_PB);

    int t = threadIdx.x, wid = t >> 5, lid = t & 31;
    int mwid = wid & 3, nhalf = wid >> 2;
    int h = blockIdx.x, b = blockIdx.y;

    uint32_t aRowSel = (lid & 7) + ((lid >> 3) & 1) * 8;
    uint32_t aColSel = ((lid >> 4) & 1) * 16;
    uint32_t swz = (lid & 7) * 16;

    const float4* xb4 = (const float4*)(g_xt + (size_t)b*PIX*CC);

    float acc[32];
#pragma unroll
    for (int i = 0; i < 32; i++) acc[i] = 0.f;

#define DF_PARAMS(kk_, psel_) do {                                               \
    if (t < 128) {                                                               \
        int px_ = t;                                                             \
        int pix_ = h*WW + px_;                                                   \
        float oy_ = g_offset[((size_t)(b*18 + 2*(kk_)  ))*PIX + pix_];           \
        float ox_ = g_offset[((size_t)(b*18 + 2*(kk_)+1))*PIX + pix_];           \
        float m_  = g_mask  [((size_t)(b*9  + (kk_)    ))*PIX + pix_];           \
        int ky_ = (kk_)/3, kx_ = (kk_) - ky_*3;                                  \
        float py_  = oy_ + (float)(ky_ + h - 1);                                 \
        float pxf_ = ox_ + (float)(kx_ + px_ - 1);                               \
        float y0f_ = floorf(py_), x0f_ = floorf(pxf_);                           \
        int y0_ = (int)y0f_, x0_ = (int)x0f_;                                    \
        int y1_ = y0_ + 1,   x1_ = x0_ + 1;                                      \
        float wy1_ = py_ - y0f_,  wx1_ = pxf_ - x0f_;                            \
        float wy0_ = 1.f - wy1_, wx0_ = 1.f - wx1_;                              \
        bool vy0_ = (y0_>=0 && y0_<HH), vy1_ = (y1_>=0 && y1_<HH);               \
        bool vx0_ = (x0_>=0 && x0_<WW), vx1_ = (x1_>=0 && x1_<WW);               \
        int y0c_ = min(max(y0_,0),HH-1), y1c_ = min(max(y1_,0),HH-1);            \
        int x0c_ = min(max(x0_,0),WW-1), x1c_ = min(max(x1_,0),WW-1);            \
        int base_ = (psel_)*1024 + px_*8;                                        \
        spi[base_+0] = (y0c_*WW + x0c_)*16;                                      \
        spi[base_+1] = (y0c_*WW + x1c_)*16;                                      \
        spi[base_+2] = (y1c_*WW + x0c_)*16;                                      \
        spi[base_+3] = (y1c_*WW + x1c_)*16;                                      \
        spf[base_+4] = (vy0_&&vx0_) ? wy0_*wx0_*m_ : 0.f;                        \
        spf[base_+5] = (vy0_&&vx1_) ? wy0_*wx1_*m_ : 0.f;                        \
        spf[base_+6] = (vy1_&&vx0_) ? wy1_*wx0_*m_ : 0.f;                        \
        spf[base_+7] = (vy1_&&vx1_) ? wy1_*wx1_*m_ : 0.f;                        \
    } } while(0)

#define DF_GATHER(psel_, dH_, dL_) do {                                          \
    _Pragma("unroll")                                                            \
    for (int it_ = 0; it_ < 8; it_++) {                                          \
        int j_ = it_*256 + t;                                                    \
        int px_ = j_ >> 4, l16_ = j_ & 15;                                       \
        int base_ = (psel_)*1024 + px_*8;                                        \
        int i00 = spi[base_+0], i01 = spi[base_+1], i10 = spi[base_+2], i11 = spi[base_+3]; \
        float g00 = spf[base_+4], g01 = spf[base_+5], g10 = spf[base_+6], g11 = spf[base_+7]; \
        float4 a_ = xb4[i00 + l16_];                                             \
        float4 c_ = xb4[i01 + l16_];                                             \
        float4 d_ = xb4[i10 + l16_];                                             \
        float4 e_ = xb4[i11 + l16_];                                             \
        float v0 = g00*a_.x + g01*c_.x + g10*d_.x + g11*e_.x;                    \
        float v1 = g00*a_.y + g01*c_.y + g10*d_.y + g11*e_.y;                    \
        float v2 = g00*a_.z + g01*c_.z + g10*d_.z + g11*e_.z;                    \
        float v3 = g00*a_.w + g01*c_.w + g10*d_.w + g11*e_.w;                    \
        float w0=btrunc(v0), w1=btrunc(v1), w2=btrunc(v2), w3=btrunc(v3);        \
        uint32_t off_ = px_*128 + ((l16_*8) ^ ((px_ & 7)*16));                   \
        sts2(sb + (dH_) + off_, pk(v0,v1), pk(v2,v3));                           \
        sts2(sb + (dL_) + off_, pk(v0-w0,v1-w1), pk(v2-w2,v3-w3));               \
    } } while(0)

    // prologue
    DF_PARAMS(0, 0);
    __syncthreads();
    DF_GATHER(0, DF_A0H, DF_A0L);
    DF_PARAMS(1, 1);
    __syncthreads();

    for (int kk = 0; kk < 9; kk++) {
        int cs = kk & 1, ns = cs ^ 1;
        if (kk < 8) {
            if (ns) DF_GATHER(1, DF_A1H, DF_A1L);
            else    DF_GATHER(0, DF_A0H, DF_A0L);
        }
        if (kk < 7) DF_PARAMS(kk+2, cs);

        uint32_t aH = sb + (cs ? DF_A1H : DF_A0H);
#pragma unroll
        for (int ks = 0; ks < 4; ks++) {
            int bi = (kk*16 + ks*4 + nhalf*2)*32 + lid;
            uint4 BH0 = g_dBh[bi], BH1 = g_dBh[bi + 32];
            uint4 BL0 = g_dBl[bi], BL1 = g_dBl[bi + 32];
            uint32_t ah[8], al[8];
#pragma unroll
            for (int m = 0; m < 2; m++) {
                uint32_t R = mwid*32 + m*16 + aRowSel;
                uint32_t aa = aH + R*128 + ((ks*32 + aColSel) ^ swz);
                ldsm4(ah[m*4+0], ah[m*4+1], ah[m*4+2], ah[m*4+3], aa);
                ldsm4(al[m*4+0], al[m*4+1], al[m*4+2], al[m*4+3], aa + 16384);
            }
#pragma unroll
            for (int m = 0; m < 2; m++) {
                float* d0 = acc + (m*4+0)*4;
                float* d1 = acc + (m*4+1)*4;
                float* d2 = acc + (m*4+2)*4;
                float* d3 = acc + (m*4+3)*4;
                mma16816(d0, ah[m*4+0],ah[m*4+1],ah[m*4+2],ah[m*4+3], BH0.x, BH0.y);
                mma16816(d0, al[m*4+0],al[m*4+1],al[m*4+2],al[m*4+3], BH0.x, BH0.y);
                mma16816(d0, ah[m*4+0],ah[m*4+1],ah[m*4+2],ah[m*4+3], BL0.x, BL0.y);
                mma16816(d1, ah[m*4+0],ah[m*4+1],ah[m*4+2],ah[m*4+3], BH0.z, BH0.w);
                mma16816(d1, al[m*4+0],al[m*4+1],al[m*4+2],al[m*4+3], BH0.z, BH0.w);
                mma16816(d1, ah[m*4+0],ah[m*4+1],ah[m*4+2],ah[m*4+3], BL0.z, BL0.w);
                mma16816(d2, ah[m*4+0],ah[m*4+1],ah[m*4+2],ah[m*4+3], BH1.x, BH1.y);
                mma16816(d2, al[m*4+0],al[m*4+1],al[m*4+2],al[m*4+3], BH1.x, BH1.y);
                mma16816(d2, ah[m*4+0],ah[m*4+1],ah[m*4+2],ah[m*4+3], BL1.x, BL1.y);
                mma16816(d3, ah[m*4+0],ah[m*4+1],ah[m*4+2],ah[m*4+3], BH1.z, BH1.w);
                mma16816(d3, al[m*4+0],al[m*4+1],al[m*4+2],al[m*4+3], BH1.z, BH1.w);
                mma16816(d3, ah[m*4+0],ah[m*4+1],ah[m*4+2],ah[m*4+3], BL1.z, BL1.w);
            }
        }
        __syncthreads();
    }

    // epilogue
    int g = lid >> 2, tig = lid & 3;
    size_t ob = (size_t)b*64*PIX + (size_t)h*WW;
#pragma unroll
    for (int n = 0; n < 4; n++)
#pragma unroll
    for (int m = 0; m < 2; m++)
#pragma unroll
    for (int r = 0; r < 4; r++) {
        int px = mwid*32 + m*16 + g + (r>>1)*8;
        int oc = nhalf*32 + n*8 + 2*tig + (r&1);
        out[ob + (size_t)oc*PIX + px] = acc[(m*4+n)*4 + r];
    }
}

// ---------------------------------------------------------------------------
extern "C" void kernel_launch(void* const* d_in, const int* in_sizes, int n_in,
                              void* d_out, int out_size)
{
    const float* x     = (const float*)d_in[0];
    const float* guide = (const float*)d_in[1];
    const float* w_off = (const float*)d_in[2];
    const float* b_off = (const float*)d_in[3];
    const float* w_mod = (const float*)d_in[4];
    const float* b_mod = (const float*)d_in[5];
    const float* w_reg = (const float*)d_in[6];
    float* out = (float*)d_out;

    cudaFuncSetAttribute(k_offmod, cudaFuncAttributeMaxDynamicSharedMemorySize, OM_SMEM);
    cudaFuncSetAttribute(k_deform, cudaFuncAttributeMaxDynamicSharedMemorySize, DF_SMEM);

    k_transpose<<<dim3(HH, BB, 2), 256>>>(x, guide);
    k_prepw    <<<72, 256>>>(w_off, w_mod, w_reg);
    k_offmod   <<<dim3(HH, BB), 256, OM_SMEM>>>(b_off, b_mod);
    k_deform   <<<dim3(HH, BB), 256, DF_SMEM>>>(out);
}